// round 7
// baseline (speedup 1.0000x reference)
#include <cuda_runtime.h>
#include <cuda_bf16.h>
#include <cuda_fp16.h>
#include <cstdint>

// ---------------------------------------------------------------------------
// GCN: 3 layers, N=100000, E=1.6M, self-loops, sym-norm.
//   hs = in @ W                (fp16, UNscaled; dinv applied in gather)
//   agg[d] = dinv[d]*hs[d] + sum_{(s,d)} dinv[s]*hs[s]
//   next layer A-transform: relu(agg*dinv + b)
// CSR build runs on a forked stream, overlapped with layer-1 GEMM.
// ---------------------------------------------------------------------------

#define MAXN 100352
#define MAXE 1700000
#define FDIM 128

__device__ __half g_bufH[MAXN * FDIM];   // hs (fp16)
__device__ float  g_bufB[MAXN * FDIM];   // agg (fp32)
__device__ float  g_dinv[MAXN];
__device__ int    g_deg[MAXN];
__device__ int    g_cursor[MAXN];
__device__ int    g_rowptr[MAXN];
__device__ int    g_bsum[256];
__device__ int    g_srcsorted[MAXE];
// W fp16 b-fragments: [na(16)][kb(8)][lane(32)][reg(2)] of uint(=half2)
__device__ unsigned g_W1f[8192];
__device__ unsigned g_W2f[8192];

// ---------------------------------------------------------------------------
__device__ __forceinline__ unsigned pack_half2(float x, float y) {
    __half2 h = __floats2half2_rn(x, y);
    unsigned u;
    asm("mov.b32 %0, %1;" : "=r"(u) : "r"(*(unsigned*)&h));
    return u;
}

__device__ __forceinline__ void mma_f16(float* d, const unsigned* a, const unsigned* b) {
    asm volatile(
        "mma.sync.aligned.m16n8k16.row.col.f32.f16.f16.f32 "
        "{%0,%1,%2,%3}, {%4,%5,%6,%7}, {%8,%9}, {%0,%1,%2,%3};\n"
        : "+f"(d[0]), "+f"(d[1]), "+f"(d[2]), "+f"(d[3])
        : "r"(a[0]), "r"(a[1]), "r"(a[2]), "r"(a[3]), "r"(b[0]), "r"(b[1]));
}

// ---------------------------------------------------------------------------
// CSR construction
// ---------------------------------------------------------------------------
__global__ void zero_kernel(int* deg, int M) {
    int i = blockIdx.x * blockDim.x + threadIdx.x;
    if (i < M) deg[i] = 0;
}

__global__ void deg_count_kernel(const int* __restrict__ dst, int* deg, int E) {
    int i = (blockIdx.x * blockDim.x + threadIdx.x) * 4;
    if (i + 3 < E) {
        int4 d = *(const int4*)(dst + i);
        atomicAdd(&deg[d.x], 1);
        atomicAdd(&deg[d.y], 1);
        atomicAdd(&deg[d.z], 1);
        atomicAdd(&deg[d.w], 1);
    } else {
        for (int j = i; j < E; j++) atomicAdd(&deg[dst[j]], 1);
    }
}

__global__ void dinv_kernel(const int* __restrict__ deg, float* dinv, int M) {
    int i = blockIdx.x * blockDim.x + threadIdx.x;
    if (i < M) dinv[i] = rsqrtf((float)deg[i] + 1.0f);
}

__global__ __launch_bounds__(1024) void scan_block_kernel(
    const int* __restrict__ deg, int* row_ptr, int* bsum, int M)
{
    int gid  = blockIdx.x * 1024 + threadIdx.x;
    int lane = threadIdx.x & 31;
    int wid  = threadIdx.x >> 5;
    int v = (gid < M) ? deg[gid] : 0;
    int x = v;
    #pragma unroll
    for (int o = 1; o < 32; o <<= 1) {
        int t = __shfl_up_sync(0xffffffffu, x, o);
        if (lane >= o) x += t;
    }
    __shared__ int ws[32];
    if (lane == 31) ws[wid] = x;
    __syncthreads();
    if (wid == 0) {
        int y = ws[lane];
        #pragma unroll
        for (int o = 1; o < 32; o <<= 1) {
            int t = __shfl_up_sync(0xffffffffu, y, o);
            if (lane >= o) y += t;
        }
        ws[lane] = y;
    }
    __syncthreads();
    int base = (wid > 0) ? ws[wid - 1] : 0;
    int incl = base + x;
    if (gid < M) row_ptr[gid] = incl - v;
    if (threadIdx.x == 1023) bsum[blockIdx.x] = incl;
}

// single-warp scan over up to 128 block sums
__global__ void scan_sums_kernel(int* bsum, int nb) {
    int lane = threadIdx.x;
    int v[4];
    int base_i = lane * 4;
    #pragma unroll
    for (int j = 0; j < 4; j++)
        v[j] = (base_i + j < nb) ? bsum[base_i + j] : 0;
    int s = v[0] + v[1] + v[2] + v[3];
    int x = s;
    #pragma unroll
    for (int o = 1; o < 32; o <<= 1) {
        int t = __shfl_up_sync(0xffffffffu, x, o);
        if (lane >= o) x += t;
    }
    int excl = x - s;
    int run = excl;
    #pragma unroll
    for (int j = 0; j < 4; j++) {
        if (base_i + j < nb) bsum[base_i + j] = run;
        run += v[j];
    }
}

__global__ void add_offsets_kernel(int* row_ptr, int* cursor,
                                   const int* __restrict__ bsum, int M) {
    int gid = blockIdx.x * blockDim.x + threadIdx.x;
    if (gid < M) {
        int v = row_ptr[gid] + bsum[gid >> 10];
        row_ptr[gid] = v;
        cursor[gid]  = v;
    }
}

__global__ void bin_edges_kernel(const int* __restrict__ src, const int* __restrict__ dst,
                                 int* cursor, int* sorted_src, int E)
{
    int i = blockIdx.x * blockDim.x + threadIdx.x;
    if (i >= E) return;
    int pos = atomicAdd(&cursor[dst[i]], 1);
    sorted_src[pos] = src[i];
}

// ---------------------------------------------------------------------------
// W fragment prep: W[128k][128n] fp32 -> fp16 b-frags for mma.m16n8k16.
// ---------------------------------------------------------------------------
__global__ void wprep_kernel(const float* __restrict__ W, unsigned* Wf) {
    int idx = blockIdx.x * blockDim.x + threadIdx.x;
    if (idx >= 16384) return;
    int k = idx >> 7;
    int n = idx & 127;
    __half w = __float2half_rn(W[idx]);
    int na = n >> 3, g = n & 7;
    int kb = k >> 4, kk = k & 15;
    int q = (kk & 7) >> 1, reg = kk >> 3, h = kk & 1;
    int lane = g * 4 + q;
    __half* out = (__half*)Wf;
    out[(((na * 8 + kb) * 32 + lane) * 2 + reg) * 2 + h] = w;
}

// ---------------------------------------------------------------------------
// fp16 tensor-core GEMM: hs(half) = transform(A)[M,128] @ W[128,128]  (no dinv!)
// transform(A) = relu?(A*dinv[row] + bias[col]) if bias else A.
// Block 128 rows, 8 warps, warp grid 4(M)x2(N), warp tile 32x64.
// ---------------------------------------------------------------------------
__global__ __launch_bounds__(256, 2) void gemm_f16_kernel(
    const float* __restrict__ A, const unsigned* __restrict__ Wf,
    const float* __restrict__ dinv, const float* __restrict__ bias, int relu,
    __half* __restrict__ hs, int M)
{
    extern __shared__ unsigned As[];   // 8192 uints = 32KB

    const int tid  = threadIdx.x;
    const int lane = tid & 31;
    const int warp = tid >> 5;
    const int block_row = blockIdx.x * 128;

    // ---- stage A tile (fp32 -> fp16 frag order) ----
    #pragma unroll
    for (int it = 0; it < 16; it++) {
        int idx = it * 256 + tid;
        int m  = idx >> 5;
        int kq = idx & 31;
        int grow = block_row + m;
        float4 v = make_float4(0.f, 0.f, 0.f, 0.f);
        if (grow < M) {
            v = *(const float4*)(A + (size_t)grow * 128 + kq * 4);
            if (bias) {
                float s = __ldg(dinv + grow);
                float4 bb = *(const float4*)(bias + kq * 4);
                v.x = v.x * s + bb.x; v.y = v.y * s + bb.y;
                v.z = v.z * s + bb.z; v.w = v.w * s + bb.w;
                if (relu) {
                    v.x = fmaxf(v.x, 0.f); v.y = fmaxf(v.y, 0.f);
                    v.z = fmaxf(v.z, 0.f); v.w = fmaxf(v.w, 0.f);
                }
            }
        }
        unsigned u0 = pack_half2(v.x, v.y);
        unsigned u1 = pack_half2(v.z, v.w);

        int ma = m >> 4;
        int g  = m & 7;
        int hi = (m >> 3) & 1;
        int kb = kq >> 2;
        int kk = (kq & 3) * 4;
        int q  = (kk & 7) >> 1;
        int reg = hi + 2 * (kk >> 3);
        int base = ((ma * 8 + kb) * 32) * 4;
        int l0 = ((g * 4 + q)     + kb * 4) & 31;
        int l1 = ((g * 4 + q + 1) + kb * 4) & 31;
        As[base + l0 * 4 + reg] = u0;
        As[base + l1 * 4 + reg] = u1;
    }
    __syncthreads();

    // ---- mainloop ----
    const int warp_m = warp >> 1;
    const int warp_n = warp & 1;

    float acc[2][8][4];
    #pragma unroll
    for (int i = 0; i < 2; i++)
        #pragma unroll
        for (int j = 0; j < 8; j++)
            #pragma unroll
            for (int r = 0; r < 4; r++) acc[i][j][r] = 0.0f;

    #pragma unroll
    for (int kb = 0; kb < 8; kb++) {
        int lane_s = (lane + kb * 4) & 31;
        unsigned a[2][4];
        #pragma unroll
        for (int i = 0; i < 2; i++) {
            int ma = warp_m * 2 + i;
            uint4 av = *(const uint4*)(As + ((ma * 8 + kb) * 32 + lane_s) * 4);
            a[i][0] = av.x; a[i][1] = av.y; a[i][2] = av.z; a[i][3] = av.w;
        }
        #pragma unroll
        for (int j = 0; j < 8; j++) {
            int na = warp_n * 8 + j;
            uint2 b2 = __ldg((const uint2*)(Wf + ((size_t)(na * 8 + kb) * 32 + lane) * 2));
            unsigned b[2] = {b2.x, b2.y};
            mma_f16(acc[0][j], a[0], b);
            mma_f16(acc[1][j], a[1], b);
        }
    }

    // ---- epilogue: store fp16 (unscaled) ----
    int g  = lane >> 2;
    int qc = lane & 3;
    #pragma unroll
    for (int i = 0; i < 2; i++) {
        int r0 = block_row + warp_m * 32 + i * 16 + g;
        int r1 = r0 + 8;
        #pragma unroll
        for (int j = 0; j < 8; j++) {
            int col = warp_n * 64 + j * 8 + qc * 2;
            if (r0 < M) {
                unsigned u = pack_half2(acc[i][j][0], acc[i][j][1]);
                *(unsigned*)(hs + (size_t)r0 * 128 + col) = u;
            }
            if (r1 < M) {
                unsigned u = pack_half2(acc[i][j][2], acc[i][j][3]);
                *(unsigned*)(hs + (size_t)r1 * 128 + col) = u;
            }
        }
    }
}

// ---------------------------------------------------------------------------
// Aggregation: one warp per dst node; gathers dinv[s]*hs[s], fp32 accumulate.
// ---------------------------------------------------------------------------
__global__ __launch_bounds__(256) void agg_kernel(
    const int* __restrict__ sorted_src, const int* __restrict__ row_ptr,
    const int* __restrict__ deg, const float* __restrict__ dinv,
    const __half* __restrict__ hs, float* __restrict__ agg, int M)
{
    int node = (blockIdx.x * 256 + threadIdx.x) >> 5;
    int lane = threadIdx.x & 31;
    if (node >= M) return;

    int beg = __ldg(row_ptr + node);
    int cnt = __ldg(deg + node);

    const uint2* hsrow = (const uint2*)hs;   // 32 uint2 per row

    float4 acc;
    {
        float dv = __ldg(dinv + node);
        uint2 v = __ldg(hsrow + (size_t)node * 32 + lane);
        float2 a = __half22float2(*(__half2*)&v.x);
        float2 b = __half22float2(*(__half2*)&v.y);
        acc = make_float4(a.x * dv, a.y * dv, b.x * dv, b.y * dv);
    }

    int e = 0;
    while (e < cnt) {
        int batch = min(32, cnt - e);
        int s = (lane < batch) ? __ldg(sorted_src + beg + e + lane) : 0;
        float dv = __ldg(dinv + s);
        int j = 0;
        for (; j + 4 <= batch; j += 4) {
            int s0 = __shfl_sync(0xffffffffu, s, j + 0);
            int s1 = __shfl_sync(0xffffffffu, s, j + 1);
            int s2 = __shfl_sync(0xffffffffu, s, j + 2);
            int s3 = __shfl_sync(0xffffffffu, s, j + 3);
            float w0 = __shfl_sync(0xffffffffu, dv, j + 0);
            float w1 = __shfl_sync(0xffffffffu, dv, j + 1);
            float w2 = __shfl_sync(0xffffffffu, dv, j + 2);
            float w3 = __shfl_sync(0xffffffffu, dv, j + 3);
            uint2 v0 = __ldg(hsrow + (size_t)s0 * 32 + lane);
            uint2 v1 = __ldg(hsrow + (size_t)s1 * 32 + lane);
            uint2 v2 = __ldg(hsrow + (size_t)s2 * 32 + lane);
            uint2 v3 = __ldg(hsrow + (size_t)s3 * 32 + lane);
            float2 a0 = __half22float2(*(__half2*)&v0.x), b0 = __half22float2(*(__half2*)&v0.y);
            float2 a1 = __half22float2(*(__half2*)&v1.x), b1 = __half22float2(*(__half2*)&v1.y);
            float2 a2 = __half22float2(*(__half2*)&v2.x), b2 = __half22float2(*(__half2*)&v2.y);
            float2 a3 = __half22float2(*(__half2*)&v3.x), b3 = __half22float2(*(__half2*)&v3.y);
            acc.x = fmaf(w0, a0.x, fmaf(w1, a1.x, fmaf(w2, a2.x, fmaf(w3, a3.x, acc.x))));
            acc.y = fmaf(w0, a0.y, fmaf(w1, a1.y, fmaf(w2, a2.y, fmaf(w3, a3.y, acc.y))));
            acc.z = fmaf(w0, b0.x, fmaf(w1, b1.x, fmaf(w2, b2.x, fmaf(w3, b3.x, acc.z))));
            acc.w = fmaf(w0, b0.y, fmaf(w1, b1.y, fmaf(w2, b2.y, fmaf(w3, b3.y, acc.w))));
        }
        for (; j < batch; j++) {
            int sj = __shfl_sync(0xffffffffu, s, j);
            float wj = __shfl_sync(0xffffffffu, dv, j);
            uint2 v = __ldg(hsrow + (size_t)sj * 32 + lane);
            float2 a = __half22float2(*(__half2*)&v.x);
            float2 b = __half22float2(*(__half2*)&v.y);
            acc.x = fmaf(wj, a.x, acc.x); acc.y = fmaf(wj, a.y, acc.y);
            acc.z = fmaf(wj, b.x, acc.z); acc.w = fmaf(wj, b.y, acc.w);
        }
        e += batch;
    }

    *((float4*)(agg + (size_t)node * 128) + lane) = acc;
}

// ---------------------------------------------------------------------------
// Output GEMM: out[M,40] = (A*dinv + b2) @ Wout + bout
// ---------------------------------------------------------------------------
__global__ __launch_bounds__(128) void gemm_out_kernel(
    const float* __restrict__ A, const float* __restrict__ W,
    const float* __restrict__ dinv, const float* __restrict__ bias2,
    const float* __restrict__ bout, float* __restrict__ out, int M)
{
    __shared__ float As2[128][64];
    __shared__ float Ws[128 * 40];

    const int rb  = blockIdx.x * 64;
    const int tid = threadIdx.x;

    for (int i = tid; i < 128 * 40; i += 128) Ws[i] = W[i];

    for (int i = tid; i < 64 * 32; i += 128) {
        int r  = i >> 5;
        int c4 = i & 31;
        int grow = rb + r;
        float4 v = make_float4(0.f, 0.f, 0.f, 0.f);
        if (grow < M) {
            v = *(const float4*)(A + (size_t)grow * 128 + c4 * 4);
            float s = __ldg(dinv + grow);
            float4 bb = *(const float4*)(bias2 + c4 * 4);
            v.x = v.x * s + bb.x; v.y = v.y * s + bb.y;
            v.z = v.z * s + bb.z; v.w = v.w * s + bb.w;
        }
        As2[c4 * 4 + 0][r] = v.x;
        As2[c4 * 4 + 1][r] = v.y;
        As2[c4 * 4 + 2][r] = v.z;
        As2[c4 * 4 + 3][r] = v.w;
    }
    __syncthreads();

    const int tcol = tid & 7;
    const int trow = tid >> 3;
    float acc[4][5];
    #pragma unroll
    for (int i = 0; i < 4; i++)
        #pragma unroll
        for (int j = 0; j < 5; j++) acc[i][j] = 0.0f;

    #pragma unroll 4
    for (int k = 0; k < 128; k++) {
        float a[4], w[5];
        #pragma unroll
        for (int i = 0; i < 4; i++) a[i] = As2[k][trow * 4 + i];
        #pragma unroll
        for (int j = 0; j < 5; j++) w[j] = Ws[k * 40 + tcol * 5 + j];
        #pragma unroll
        for (int i = 0; i < 4; i++)
            #pragma unroll
            for (int j = 0; j < 5; j++) acc[i][j] += a[i] * w[j];
    }

    #pragma unroll
    for (int i = 0; i < 4; i++) {
        int grow = rb + trow * 4 + i;
        if (grow >= M) break;
        #pragma unroll
        for (int j = 0; j < 5; j++) {
            int c = tcol * 5 + j;
            out[(size_t)grow * 40 + c] = acc[i][j] + __ldg(bout + c);
        }
    }
}

// ---------------------------------------------------------------------------

extern "C" void kernel_launch(void* const* d_in, const int* in_sizes, int n_in,
                              void* d_out, int out_size)
{
    const float* x    = (const float*)d_in[0];
    const int*   ei   = (const int*)d_in[1];
    const float* W1   = (const float*)d_in[2];
    const float* b1   = (const float*)d_in[3];
    const float* W2   = (const float*)d_in[4];
    const float* b2   = (const float*)d_in[5];
    const float* Wout = (const float*)d_in[6];
    const float* bout = (const float*)d_in[7];
    float* out = (float*)d_out;

    const int M = in_sizes[0] / FDIM;
    const int E = in_sizes[1] / 2;
    const int* src = ei;
    const int* dst = ei + E;

    __half* bufH;
    float *bufB, *dinv;
    unsigned *w1f, *w2f;
    int *deg, *cursor, *rowptr, *bsum, *srcsorted;
    cudaGetSymbolAddress((void**)&bufH, g_bufH);
    cudaGetSymbolAddress((void**)&bufB, g_bufB);
    cudaGetSymbolAddress((void**)&dinv, g_dinv);
    cudaGetSymbolAddress((void**)&deg, g_deg);
    cudaGetSymbolAddress((void**)&cursor, g_cursor);
    cudaGetSymbolAddress((void**)&rowptr, g_rowptr);
    cudaGetSymbolAddress((void**)&bsum, g_bsum);
    cudaGetSymbolAddress((void**)&srcsorted, g_srcsorted);
    cudaGetSymbolAddress((void**)&w1f, g_W1f);
    cudaGetSymbolAddress((void**)&w2f, g_W2f);

    static int inited = 0;
    static cudaStream_t s2;
    static cudaEvent_t evFork, evJoin;
    if (!inited) {
        cudaFuncSetAttribute(gemm_f16_kernel,
                             cudaFuncAttributeMaxDynamicSharedMemorySize, 32768);
        cudaStreamCreateWithFlags(&s2, cudaStreamNonBlocking);
        cudaEventCreateWithFlags(&evFork, cudaEventDisableTiming);
        cudaEventCreateWithFlags(&evJoin, cudaEventDisableTiming);
        inited = 1;
    }

    const int nb_nodes = (M + 255) / 256;
    const int nb_edges = (E + 255) / 256;
    const int nb_edge4 = (E + 1023) / 1024;
    const int nb_scan  = (M + 1023) / 1024;
    const int nb_gemm  = (M + 127) / 128;
    const int nb_agg   = (M + 7) / 8;
    const int nb_gout  = (M + 63) / 64;

    // --- fork: CSR build chain on s2, overlapped with wprep + layer-1 GEMM ---
    cudaEventRecord(evFork, 0);
    cudaStreamWaitEvent(s2, evFork, 0);
    zero_kernel<<<nb_nodes, 256, 0, s2>>>(deg, M);
    deg_count_kernel<<<nb_edge4, 256, 0, s2>>>(dst, deg, E);
    dinv_kernel<<<nb_nodes, 256, 0, s2>>>(deg, dinv, M);
    scan_block_kernel<<<nb_scan, 1024, 0, s2>>>(deg, rowptr, bsum, M);
    scan_sums_kernel<<<1, 32, 0, s2>>>(bsum, nb_scan);
    add_offsets_kernel<<<nb_nodes, 256, 0, s2>>>(rowptr, cursor, bsum, M);
    bin_edges_kernel<<<nb_edges, 256, 0, s2>>>(src, dst, cursor, srcsorted, E);
    cudaEventRecord(evJoin, s2);

    // --- main stream: W prep + layer-1 GEMM (no dinv dependency) ---
    wprep_kernel<<<64, 256>>>(W1, w1f);
    wprep_kernel<<<64, 256>>>(W2, w2f);
    gemm_f16_kernel<<<nb_gemm, 256, 32768>>>(x, w1f, nullptr, nullptr, 0, bufH, M);

    // --- join: aggregation needs CSR + dinv ---
    cudaStreamWaitEvent(0, evJoin, 0);
    agg_kernel<<<nb_agg, 256>>>(srcsorted, rowptr, deg, dinv, bufH, bufB, M);

    // --- Layer 2: relu(agg1*dinv+b1) fused into A-load; hs2 -> bufH ---
    gemm_f16_kernel<<<nb_gemm, 256, 32768>>>(bufB, w2f, dinv, b1, 1, bufH, M);
    agg_kernel<<<nb_agg, 256>>>(srcsorted, rowptr, deg, dinv, bufH, bufB, M);

    // --- Output: h2 = agg2*dinv + b2 fused; out = h2 @ Wout + bout ---
    gemm_out_kernel<<<nb_gout, 128>>>(bufB, Wout, dinv, b2, bout, out, M);
}

// round 9
// speedup vs baseline: 1.2020x; 1.2020x over previous
#include <cuda_runtime.h>
#include <cuda_bf16.h>
#include <cuda_fp16.h>
#include <cstdint>

// ---------------------------------------------------------------------------
// GCN: 3 layers, N=100000, E=1.6M, self-loops, sym-norm.
//   hs = (in @ W) * dinv[row]                 (fp16, pre-scaled)
//   h  = relu?(dinv[d]*(hs[d]+Sum hs[s]) + b) (fused in agg epilogue, fp16 out)
// GEMMs read fp16 A directly (layer 2 + output). fp16 mma m16n8k16, fp32 acc.
// CSR scan/bin forked onto stream 2 under layer-1 GEMM.
// ---------------------------------------------------------------------------

#define MAXN 100352
#define MAXE 1700000
#define FDIM 128

__device__ __half g_bufH[MAXN * FDIM];    // hs (fp16, pre-scaled)
__device__ __half g_bufH2[MAXN * FDIM];   // h (fp16, finished layer output)
__device__ float  g_dinv[MAXN];
__device__ int    g_deg[MAXN];
__device__ int    g_cursor[MAXN];
__device__ int    g_rowptr[MAXN];
__device__ int    g_bsum[256];
__device__ int    g_srcsorted[MAXE];
// W fp16 b-fragments: [na(16)][kb(8)][lane(32)][reg(2)] of uint(=half2)
__device__ unsigned g_W1f[8192];
__device__ unsigned g_W2f[8192];

// ---------------------------------------------------------------------------
__device__ __forceinline__ unsigned pack_half2(float x, float y) {
    __half2 h = __floats2half2_rn(x, y);
    unsigned u;
    asm("mov.b32 %0, %1;" : "=r"(u) : "r"(*(unsigned*)&h));
    return u;
}

__device__ __forceinline__ void mma_f16(float* d, const unsigned* a, const unsigned* b) {
    asm volatile(
        "mma.sync.aligned.m16n8k16.row.col.f32.f16.f16.f32 "
        "{%0,%1,%2,%3}, {%4,%5,%6,%7}, {%8,%9}, {%0,%1,%2,%3};\n"
        : "+f"(d[0]), "+f"(d[1]), "+f"(d[2]), "+f"(d[3])
        : "r"(a[0]), "r"(a[1]), "r"(a[2]), "r"(a[3]), "r"(b[0]), "r"(b[1]));
}

// ---------------------------------------------------------------------------
// CSR construction
// ---------------------------------------------------------------------------
__global__ void zero_kernel(int* deg, int M) {
    int i = blockIdx.x * blockDim.x + threadIdx.x;
    if (i < M) deg[i] = 0;
}

__global__ void deg_count_kernel(const int* __restrict__ dst, int* deg, int E) {
    int i = (blockIdx.x * blockDim.x + threadIdx.x) * 4;
    if (i + 3 < E) {
        int4 d = *(const int4*)(dst + i);
        atomicAdd(&deg[d.x], 1);
        atomicAdd(&deg[d.y], 1);
        atomicAdd(&deg[d.z], 1);
        atomicAdd(&deg[d.w], 1);
    } else {
        for (int j = i; j < E; j++) atomicAdd(&deg[dst[j]], 1);
    }
}

__global__ void dinv_kernel(const int* __restrict__ deg, float* dinv, int M) {
    int i = blockIdx.x * blockDim.x + threadIdx.x;
    if (i < M) dinv[i] = rsqrtf((float)deg[i] + 1.0f);
}

__global__ __launch_bounds__(1024) void scan_block_kernel(
    const int* __restrict__ deg, int* row_ptr, int* bsum, int M)
{
    int gid  = blockIdx.x * 1024 + threadIdx.x;
    int lane = threadIdx.x & 31;
    int wid  = threadIdx.x >> 5;
    int v = (gid < M) ? deg[gid] : 0;
    int x = v;
    #pragma unroll
    for (int o = 1; o < 32; o <<= 1) {
        int t = __shfl_up_sync(0xffffffffu, x, o);
        if (lane >= o) x += t;
    }
    __shared__ int ws[32];
    if (lane == 31) ws[wid] = x;
    __syncthreads();
    if (wid == 0) {
        int y = ws[lane];
        #pragma unroll
        for (int o = 1; o < 32; o <<= 1) {
            int t = __shfl_up_sync(0xffffffffu, y, o);
            if (lane >= o) y += t;
        }
        ws[lane] = y;
    }
    __syncthreads();
    int base = (wid > 0) ? ws[wid - 1] : 0;
    int incl = base + x;
    if (gid < M) row_ptr[gid] = incl - v;
    if (threadIdx.x == 1023) bsum[blockIdx.x] = incl;
}

// single-warp scan over up to 128 block sums
__global__ void scan_sums_kernel(int* bsum, int nb) {
    int lane = threadIdx.x;
    int v[4];
    int base_i = lane * 4;
    #pragma unroll
    for (int j = 0; j < 4; j++)
        v[j] = (base_i + j < nb) ? bsum[base_i + j] : 0;
    int s = v[0] + v[1] + v[2] + v[3];
    int x = s;
    #pragma unroll
    for (int o = 1; o < 32; o <<= 1) {
        int t = __shfl_up_sync(0xffffffffu, x, o);
        if (lane >= o) x += t;
    }
    int excl = x - s;
    int run = excl;
    #pragma unroll
    for (int j = 0; j < 4; j++) {
        if (base_i + j < nb) bsum[base_i + j] = run;
        run += v[j];
    }
}

__global__ void add_offsets_kernel(int* row_ptr, int* cursor,
                                   const int* __restrict__ bsum, int M) {
    int gid = blockIdx.x * blockDim.x + threadIdx.x;
    if (gid < M) {
        int v = row_ptr[gid] + bsum[gid >> 10];
        row_ptr[gid] = v;
        cursor[gid]  = v;
    }
}

__global__ void bin_edges_kernel(const int* __restrict__ src, const int* __restrict__ dst,
                                 int* cursor, int* sorted_src, int E)
{
    int i = blockIdx.x * blockDim.x + threadIdx.x;
    if (i >= E) return;
    int pos = atomicAdd(&cursor[dst[i]], 1);
    sorted_src[pos] = src[i];
}

// ---------------------------------------------------------------------------
// W fragment prep: W[128k][128n] fp32 -> fp16 b-frags for mma.m16n8k16.
// ---------------------------------------------------------------------------
__global__ void wprep_kernel(const float* __restrict__ W, unsigned* Wf) {
    int idx = blockIdx.x * blockDim.x + threadIdx.x;
    if (idx >= 16384) return;
    int k = idx >> 7;
    int n = idx & 127;
    __half w = __float2half_rn(W[idx]);
    int na = n >> 3, g = n & 7;
    int kb = k >> 4, kk = k & 15;
    int q = (kk & 7) >> 1, reg = kk >> 3, h = kk & 1;
    int lane = g * 4 + q;
    __half* out = (__half*)Wf;
    out[(((na * 8 + kb) * 32 + lane) * 2 + reg) * 2 + h] = w;
}

// ---------------------------------------------------------------------------
// fp16 tensor-core GEMM: hs(half) = A[M,128] @ W[128,128] * dinv[row].
// A is fp32 (a_is_half=0) or fp16 (a_is_half=1); no input transform.
// Block 128 rows, 8 warps, warp grid 4(M)x2(N), warp tile 32x64.
// ---------------------------------------------------------------------------
__global__ __launch_bounds__(256, 2) void gemm_f16_kernel(
    const void* __restrict__ Ap, int a_is_half, const unsigned* __restrict__ Wf,
    const float* __restrict__ dinv, __half* __restrict__ hs, int M)
{
    extern __shared__ unsigned As[];   // 8192 uints = 32KB

    const int tid  = threadIdx.x;
    const int lane = tid & 31;
    const int warp = tid >> 5;
    const int block_row = blockIdx.x * 128;

    // ---- stage A tile into fp16 frag-order smem ----
    #pragma unroll
    for (int it = 0; it < 16; it++) {
        int idx = it * 256 + tid;
        int m  = idx >> 5;           // row in tile
        int kq = idx & 31;           // 4-element group along K
        int grow = block_row + m;
        unsigned u0 = 0, u1 = 0;
        if (grow < M) {
            if (a_is_half) {
                uint2 v = *(const uint2*)((const __half*)Ap + (size_t)grow * 128 + kq * 4);
                u0 = v.x; u1 = v.y;
            } else {
                float4 v = *(const float4*)((const float*)Ap + (size_t)grow * 128 + kq * 4);
                u0 = pack_half2(v.x, v.y);
                u1 = pack_half2(v.z, v.w);
            }
        }
        int ma = m >> 4;
        int g  = m & 7;
        int hi = (m >> 3) & 1;
        int kb = kq >> 2;
        int kk = (kq & 3) * 4;
        int q  = (kk & 7) >> 1;
        int reg = hi + 2 * (kk >> 3);
        int base = ((ma * 8 + kb) * 32) * 4;
        int l0 = ((g * 4 + q)     + kb * 4) & 31;
        int l1 = ((g * 4 + q + 1) + kb * 4) & 31;
        As[base + l0 * 4 + reg] = u0;
        As[base + l1 * 4 + reg] = u1;
    }
    __syncthreads();

    // ---- mainloop ----
    const int warp_m = warp >> 1;
    const int warp_n = warp & 1;

    float acc[2][8][4];
    #pragma unroll
    for (int i = 0; i < 2; i++)
        #pragma unroll
        for (int j = 0; j < 8; j++)
            #pragma unroll
            for (int r = 0; r < 4; r++) acc[i][j][r] = 0.0f;

    #pragma unroll
    for (int kb = 0; kb < 8; kb++) {
        int lane_s = (lane + kb * 4) & 31;
        unsigned a[2][4];
        #pragma unroll
        for (int i = 0; i < 2; i++) {
            int ma = warp_m * 2 + i;
            uint4 av = *(const uint4*)(As + ((ma * 8 + kb) * 32 + lane_s) * 4);
            a[i][0] = av.x; a[i][1] = av.y; a[i][2] = av.z; a[i][3] = av.w;
        }
        #pragma unroll
        for (int j = 0; j < 8; j++) {
            int na = warp_n * 8 + j;
            uint2 b2 = __ldg((const uint2*)(Wf + ((size_t)(na * 8 + kb) * 32 + lane) * 2));
            unsigned b[2] = {b2.x, b2.y};
            mma_f16(acc[0][j], a[0], b);
            mma_f16(acc[1][j], a[1], b);
        }
    }

    // ---- epilogue: scale rows by dinv, store fp16 ----
    int g  = lane >> 2;
    int qc = lane & 3;
    #pragma unroll
    for (int i = 0; i < 2; i++) {
        int r0 = block_row + warp_m * 32 + i * 16 + g;
        int r1 = r0 + 8;
        float s0 = (r0 < M) ? __ldg(dinv + r0) : 0.f;
        float s1 = (r1 < M) ? __ldg(dinv + r1) : 0.f;
        #pragma unroll
        for (int j = 0; j < 8; j++) {
            int col = warp_n * 64 + j * 8 + qc * 2;
            if (r0 < M) {
                unsigned u = pack_half2(acc[i][j][0] * s0, acc[i][j][1] * s0);
                *(unsigned*)(hs + (size_t)r0 * 128 + col) = u;
            }
            if (r1 < M) {
                unsigned u = pack_half2(acc[i][j][2] * s1, acc[i][j][3] * s1);
                *(unsigned*)(hs + (size_t)r1 * 128 + col) = u;
            }
        }
    }
}

// ---------------------------------------------------------------------------
// Aggregation + fused finalize: one warp per dst node.
//   acc = hs[d] + Sum_{s in CSR[d]} hs[s]   (fp32 accumulate, pure sum)
//   h[d] = relu?(acc * dinv[d] + bias)      (fp16 out)
// ---------------------------------------------------------------------------
__global__ __launch_bounds__(256) void agg_kernel(
    const int* __restrict__ sorted_src, const int* __restrict__ row_ptr,
    const int* __restrict__ deg, const float* __restrict__ dinv,
    const float* __restrict__ bias, int relu,
    const __half* __restrict__ hs, __half* __restrict__ h_out, int M)
{
    int node = (blockIdx.x * 256 + threadIdx.x) >> 5;
    int lane = threadIdx.x & 31;
    if (node >= M) return;

    int beg = __ldg(row_ptr + node);
    int cnt = __ldg(deg + node);

    const uint2* hsrow = (const uint2*)hs;   // 32 uint2 per row

    float4 acc;
    {
        uint2 v = __ldg(hsrow + (size_t)node * 32 + lane);
        float2 a = __half22float2(*(__half2*)&v.x);
        float2 b = __half22float2(*(__half2*)&v.y);
        acc = make_float4(a.x, a.y, b.x, b.y);
    }

    int e = 0;
    while (e < cnt) {
        int batch = min(32, cnt - e);
        int s = (lane < batch) ? __ldg(sorted_src + beg + e + lane) : 0;
        int j = 0;
        for (; j + 4 <= batch; j += 4) {
            int s0 = __shfl_sync(0xffffffffu, s, j + 0);
            int s1 = __shfl_sync(0xffffffffu, s, j + 1);
            int s2 = __shfl_sync(0xffffffffu, s, j + 2);
            int s3 = __shfl_sync(0xffffffffu, s, j + 3);
            uint2 v0 = __ldg(hsrow + (size_t)s0 * 32 + lane);
            uint2 v1 = __ldg(hsrow + (size_t)s1 * 32 + lane);
            uint2 v2 = __ldg(hsrow + (size_t)s2 * 32 + lane);
            uint2 v3 = __ldg(hsrow + (size_t)s3 * 32 + lane);
            float2 a0 = __half22float2(*(__half2*)&v0.x), b0 = __half22float2(*(__half2*)&v0.y);
            float2 a1 = __half22float2(*(__half2*)&v1.x), b1 = __half22float2(*(__half2*)&v1.y);
            float2 a2 = __half22float2(*(__half2*)&v2.x), b2 = __half22float2(*(__half2*)&v2.y);
            float2 a3 = __half22float2(*(__half2*)&v3.x), b3 = __half22float2(*(__half2*)&v3.y);
            acc.x += a0.x + a1.x + a2.x + a3.x;
            acc.y += a0.y + a1.y + a2.y + a3.y;
            acc.z += b0.x + b1.x + b2.x + b3.x;
            acc.w += b0.y + b1.y + b2.y + b3.y;
        }
        for (; j < batch; j++) {
            int sj = __shfl_sync(0xffffffffu, s, j);
            uint2 v = __ldg(hsrow + (size_t)sj * 32 + lane);
            float2 a = __half22float2(*(__half2*)&v.x);
            float2 b = __half22float2(*(__half2*)&v.y);
            acc.x += a.x; acc.y += a.y; acc.z += b.x; acc.w += b.y;
        }
        e += batch;
    }

    // fused finalize
    float dv = __ldg(dinv + node);
    float4 bb = *((const float4*)bias + lane);
    float h0 = acc.x * dv + bb.x;
    float h1 = acc.y * dv + bb.y;
    float h2 = acc.z * dv + bb.z;
    float h3 = acc.w * dv + bb.w;
    if (relu) {
        h0 = fmaxf(h0, 0.f); h1 = fmaxf(h1, 0.f);
        h2 = fmaxf(h2, 0.f); h3 = fmaxf(h3, 0.f);
    }
    uint2 o;
    o.x = pack_half2(h0, h1);
    o.y = pack_half2(h2, h3);
    *((uint2*)h_out + (size_t)node * 32 + lane) = o;
}

// ---------------------------------------------------------------------------
// Output GEMM: out[M,40] = A(half)[M,128] @ Wout + bout
// ---------------------------------------------------------------------------
__global__ __launch_bounds__(128) void gemm_out_kernel(
    const __half* __restrict__ A, const float* __restrict__ W,
    const float* __restrict__ bout, float* __restrict__ out, int M)
{
    __shared__ float As2[128][64];
    __shared__ float Ws[128 * 40];

    const int rb  = blockIdx.x * 64;
    const int tid = threadIdx.x;

    for (int i = tid; i < 128 * 40; i += 128) Ws[i] = W[i];

    for (int i = tid; i < 64 * 32; i += 128) {
        int r  = i >> 5;
        int c4 = i & 31;
        int grow = rb + r;
        float4 v = make_float4(0.f, 0.f, 0.f, 0.f);
        if (grow < M) {
            uint2 u = *(const uint2*)(A + (size_t)grow * 128 + c4 * 4);
            float2 a = __half22float2(*(__half2*)&u.x);
            float2 b = __half22float2(*(__half2*)&u.y);
            v = make_float4(a.x, a.y, b.x, b.y);
        }
        As2[c4 * 4 + 0][r] = v.x;
        As2[c4 * 4 + 1][r] = v.y;
        As2[c4 * 4 + 2][r] = v.z;
        As2[c4 * 4 + 3][r] = v.w;
    }
    __syncthreads();

    const int tcol = tid & 7;
    const int trow = tid >> 3;
    float acc[4][5];
    #pragma unroll
    for (int i = 0; i < 4; i++)
        #pragma unroll
        for (int j = 0; j < 5; j++) acc[i][j] = 0.0f;

    #pragma unroll 4
    for (int k = 0; k < 128; k++) {
        float a[4], w[5];
        #pragma unroll
        for (int i = 0; i < 4; i++) a[i] = As2[k][trow * 4 + i];
        #pragma unroll
        for (int j = 0; j < 5; j++) w[j] = Ws[k * 40 + tcol * 5 + j];
        #pragma unroll
        for (int i = 0; i < 4; i++)
            #pragma unroll
            for (int j = 0; j < 5; j++) acc[i][j] += a[i] * w[j];
    }

    #pragma unroll
    for (int i = 0; i < 4; i++) {
        int grow = rb + trow * 4 + i;
        if (grow >= M) break;
        #pragma unroll
        for (int j = 0; j < 5; j++) {
            int c = tcol * 5 + j;
            out[(size_t)grow * 40 + c] = acc[i][j] + __ldg(bout + c);
        }
    }
}

// ---------------------------------------------------------------------------

extern "C" void kernel_launch(void* const* d_in, const int* in_sizes, int n_in,
                              void* d_out, int out_size)
{
    const float* x    = (const float*)d_in[0];
    const int*   ei   = (const int*)d_in[1];
    const float* W1   = (const float*)d_in[2];
    const float* b1   = (const float*)d_in[3];
    const float* W2   = (const float*)d_in[4];
    const float* b2   = (const float*)d_in[5];
    const float* Wout = (const float*)d_in[6];
    const float* bout = (const float*)d_in[7];
    float* out = (float*)d_out;

    const int M = in_sizes[0] / FDIM;
    const int E = in_sizes[1] / 2;
    const int* src = ei;
    const int* dst = ei + E;

    __half *bufH, *bufH2;
    float *dinv;
    unsigned *w1f, *w2f;
    int *deg, *cursor, *rowptr, *bsum, *srcsorted;
    cudaGetSymbolAddress((void**)&bufH, g_bufH);
    cudaGetSymbolAddress((void**)&bufH2, g_bufH2);
    cudaGetSymbolAddress((void**)&dinv, g_dinv);
    cudaGetSymbolAddress((void**)&deg, g_deg);
    cudaGetSymbolAddress((void**)&cursor, g_cursor);
    cudaGetSymbolAddress((void**)&rowptr, g_rowptr);
    cudaGetSymbolAddress((void**)&bsum, g_bsum);
    cudaGetSymbolAddress((void**)&srcsorted, g_srcsorted);
    cudaGetSymbolAddress((void**)&w1f, g_W1f);
    cudaGetSymbolAddress((void**)&w2f, g_W2f);

    static int inited = 0;
    static cudaStream_t s2;
    static cudaEvent_t evFork, evJoin;
    if (!inited) {
        cudaFuncSetAttribute(gemm_f16_kernel,
                             cudaFuncAttributeMaxDynamicSharedMemorySize, 32768);
        cudaStreamCreateWithFlags(&s2, cudaStreamNonBlocking);
        cudaEventCreateWithFlags(&evFork, cudaEventDisableTiming);
        cudaEventCreateWithFlags(&evJoin, cudaEventDisableTiming);
        inited = 1;
    }

    const int nb_nodes = (M + 255) / 256;
    const int nb_edges = (E + 255) / 256;
    const int nb_edge4 = (E + 1023) / 1024;
    const int nb_scan  = (M + 1023) / 1024;
    const int nb_gemm  = (M + 127) / 128;
    const int nb_agg   = (M + 7) / 8;
    const int nb_gout  = (M + 63) / 64;

    // --- degrees + dinv (needed by gemm1 epilogue) ---
    zero_kernel<<<nb_nodes, 256>>>(deg, M);
    deg_count_kernel<<<nb_edge4, 256>>>(dst, deg, E);
    dinv_kernel<<<nb_nodes, 256>>>(deg, dinv, M);

    // --- fork: scan/bin chain on s2, overlapped with wprep + gemm1 ---
    cudaEventRecord(evFork, 0);
    cudaStreamWaitEvent(s2, evFork, 0);
    scan_block_kernel<<<nb_scan, 1024, 0, s2>>>(deg, rowptr, bsum, M);
    scan_sums_kernel<<<1, 32, 0, s2>>>(bsum, nb_scan);
    add_offsets_kernel<<<nb_nodes, 256, 0, s2>>>(rowptr, cursor, bsum, M);
    bin_edges_kernel<<<nb_edges, 256, 0, s2>>>(src, dst, cursor, srcsorted, E);
    cudaEventRecord(evJoin, s2);

    // --- main: W prep + layer-1 GEMM (fp32 A = x) ---
    wprep_kernel<<<64, 256>>>(W1, w1f);
    wprep_kernel<<<64, 256>>>(W2, w2f);
    gemm_f16_kernel<<<nb_gemm, 256, 32768>>>(x, 0, w1f, dinv, bufH, M);

    // --- join; layer-1 aggregation + finalize -> h1 (fp16) ---
    cudaStreamWaitEvent(0, evJoin, 0);
    agg_kernel<<<nb_agg, 256>>>(srcsorted, rowptr, deg, dinv, b1, 1, bufH, bufH2, M);

    // --- Layer 2: gemm reads fp16 h1; agg -> h2 (fp16) ---
    gemm_f16_kernel<<<nb_gemm, 256, 32768>>>(bufH2, 1, w2f, dinv, bufH, M);
    agg_kernel<<<nb_agg, 256>>>(srcsorted, rowptr, deg, dinv, b2, 0, bufH, bufH2, M);

    // --- Output projection: out = h2 @ Wout + bout ---
    gemm_out_kernel<<<nb_gout, 128>>>(bufH2, Wout, bout, out, M);
}

// round 10
// speedup vs baseline: 1.4486x; 1.2052x over previous
#include <cuda_runtime.h>
#include <cuda_bf16.h>
#include <cuda_fp16.h>
#include <cstdint>

// ---------------------------------------------------------------------------
// GCN: 3 layers, N=100000, E=1.6M, self-loops, sym-norm.
//   Layer 1: hs1 = x @ W1 (UNscaled fp16) ; h1 = relu(dinv_d*(Sum dinv_s*hs1_s) + b1)
//   Layer 2: hs2 = (h1 @ W2)*dinv_row     ; h2 = dinv_d*(Sum hs2_s) + b2
//   Out:     out = h2 @ Wout + bout        (fp16 mma, N=40)
// CSR build fully overlapped with layer-1 GEMM on a forked stream.
// ---------------------------------------------------------------------------

#define MAXN 100352
#define MAXE 1700000
#define FDIM 128

__device__ __half g_bufH[MAXN * FDIM];    // hs (fp16)
__device__ __half g_bufH2[MAXN * FDIM];   // h (fp16, finished layer output)
__device__ float  g_dinv[MAXN];
__device__ int    g_deg[MAXN];
__device__ int    g_cursor[MAXN];
__device__ int    g_rowptr[MAXN];
__device__ int    g_bsum[256];
__device__ int    g_srcsorted[MAXE];
// fp16 b-fragments: [na][kb(8)][lane(32)][reg(2)] of uint(=half2)
__device__ unsigned g_W1f[8192];
__device__ unsigned g_W2f[8192];
__device__ unsigned g_Wof[2560];          // Wout: na(5) blocks

// ---------------------------------------------------------------------------
__device__ __forceinline__ unsigned pack_half2(float x, float y) {
    __half2 h = __floats2half2_rn(x, y);
    unsigned u;
    asm("mov.b32 %0, %1;" : "=r"(u) : "r"(*(unsigned*)&h));
    return u;
}

__device__ __forceinline__ void mma_f16(float* d, const unsigned* a, const unsigned* b) {
    asm volatile(
        "mma.sync.aligned.m16n8k16.row.col.f32.f16.f16.f32 "
        "{%0,%1,%2,%3}, {%4,%5,%6,%7}, {%8,%9}, {%0,%1,%2,%3};\n"
        : "+f"(d[0]), "+f"(d[1]), "+f"(d[2]), "+f"(d[3])
        : "r"(a[0]), "r"(a[1]), "r"(a[2]), "r"(a[3]), "r"(b[0]), "r"(b[1]));
}

// ---------------------------------------------------------------------------
// CSR construction
// ---------------------------------------------------------------------------
__global__ void zero_kernel(int* deg, int M) {
    int i = blockIdx.x * blockDim.x + threadIdx.x;
    if (i < M) deg[i] = 0;
}

__global__ void deg_count_kernel(const int* __restrict__ dst, int* deg, int E) {
    int i = (blockIdx.x * blockDim.x + threadIdx.x) * 4;
    if (i + 3 < E) {
        int4 d = *(const int4*)(dst + i);
        atomicAdd(&deg[d.x], 1);
        atomicAdd(&deg[d.y], 1);
        atomicAdd(&deg[d.z], 1);
        atomicAdd(&deg[d.w], 1);
    } else {
        for (int j = i; j < E; j++) atomicAdd(&deg[dst[j]], 1);
    }
}

__global__ void dinv_kernel(const int* __restrict__ deg, float* dinv, int M) {
    int i = blockIdx.x * blockDim.x + threadIdx.x;
    if (i < M) dinv[i] = rsqrtf((float)deg[i] + 1.0f);
}

__global__ __launch_bounds__(1024) void scan_block_kernel(
    const int* __restrict__ deg, int* row_ptr, int* bsum, int M)
{
    int gid  = blockIdx.x * 1024 + threadIdx.x;
    int lane = threadIdx.x & 31;
    int wid  = threadIdx.x >> 5;
    int v = (gid < M) ? deg[gid] : 0;
    int x = v;
    #pragma unroll
    for (int o = 1; o < 32; o <<= 1) {
        int t = __shfl_up_sync(0xffffffffu, x, o);
        if (lane >= o) x += t;
    }
    __shared__ int ws[32];
    if (lane == 31) ws[wid] = x;
    __syncthreads();
    if (wid == 0) {
        int y = ws[lane];
        #pragma unroll
        for (int o = 1; o < 32; o <<= 1) {
            int t = __shfl_up_sync(0xffffffffu, y, o);
            if (lane >= o) y += t;
        }
        ws[lane] = y;
    }
    __syncthreads();
    int base = (wid > 0) ? ws[wid - 1] : 0;
    int incl = base + x;
    if (gid < M) row_ptr[gid] = incl - v;
    if (threadIdx.x == 1023) bsum[blockIdx.x] = incl;
}

__global__ void scan_sums_kernel(int* bsum, int nb) {
    int lane = threadIdx.x;
    int v[4];
    int base_i = lane * 4;
    #pragma unroll
    for (int j = 0; j < 4; j++)
        v[j] = (base_i + j < nb) ? bsum[base_i + j] : 0;
    int s = v[0] + v[1] + v[2] + v[3];
    int x = s;
    #pragma unroll
    for (int o = 1; o < 32; o <<= 1) {
        int t = __shfl_up_sync(0xffffffffu, x, o);
        if (lane >= o) x += t;
    }
    int excl = x - s;
    int run = excl;
    #pragma unroll
    for (int j = 0; j < 4; j++) {
        if (base_i + j < nb) bsum[base_i + j] = run;
        run += v[j];
    }
}

__global__ void add_offsets_kernel(int* row_ptr, int* cursor,
                                   const int* __restrict__ bsum, int M) {
    int gid = blockIdx.x * blockDim.x + threadIdx.x;
    if (gid < M) {
        int v = row_ptr[gid] + bsum[gid >> 10];
        row_ptr[gid] = v;
        cursor[gid]  = v;
    }
}

__global__ void bin_edges_kernel(const int* __restrict__ src, const int* __restrict__ dst,
                                 int* cursor, int* sorted_src, int E)
{
    int i = blockIdx.x * blockDim.x + threadIdx.x;
    if (i >= E) return;
    int pos = atomicAdd(&cursor[dst[i]], 1);
    sorted_src[pos] = src[i];
}

// ---------------------------------------------------------------------------
// W fragment prep (fp32 [K][N] -> fp16 b-frags), N = 128 or 40.
// ---------------------------------------------------------------------------
__global__ void wprep_kernel(const float* __restrict__ W, unsigned* Wf, int N) {
    int idx = blockIdx.x * blockDim.x + threadIdx.x;
    if (idx >= 128 * N) return;
    int k = idx / N;
    int n = idx % N;
    __half w = __float2half_rn(W[idx]);
    int na = n >> 3, g = n & 7;
    int kb = k >> 4, kk = k & 15;
    int q = (kk & 7) >> 1, reg = kk >> 3, h = kk & 1;
    int lane = g * 4 + q;
    __half* out = (__half*)Wf;
    out[(((na * 8 + kb) * 32 + lane) * 2 + reg) * 2 + h] = w;
}

// ---------------------------------------------------------------------------
// fp16 tensor-core GEMM: hs(half) = A[M,128] @ W[128,128] (* dinv[row] if dinv).
// A fp32 (a_is_half=0) or fp16 (a_is_half=1).
// Block 128 rows, 8 warps, warp grid 4(M)x2(N), warp tile 32x64.
// ---------------------------------------------------------------------------
__global__ __launch_bounds__(256, 2) void gemm_f16_kernel(
    const void* __restrict__ Ap, int a_is_half, const unsigned* __restrict__ Wf,
    const float* __restrict__ dinv, __half* __restrict__ hs, int M)
{
    extern __shared__ unsigned As[];   // 8192 uints = 32KB

    const int tid  = threadIdx.x;
    const int lane = tid & 31;
    const int warp = tid >> 5;
    const int block_row = blockIdx.x * 128;

    #pragma unroll
    for (int it = 0; it < 16; it++) {
        int idx = it * 256 + tid;
        int m  = idx >> 5;
        int kq = idx & 31;
        int grow = block_row + m;
        unsigned u0 = 0, u1 = 0;
        if (grow < M) {
            if (a_is_half) {
                uint2 v = *(const uint2*)((const __half*)Ap + (size_t)grow * 128 + kq * 4);
                u0 = v.x; u1 = v.y;
            } else {
                float4 v = *(const float4*)((const float*)Ap + (size_t)grow * 128 + kq * 4);
                u0 = pack_half2(v.x, v.y);
                u1 = pack_half2(v.z, v.w);
            }
        }
        int ma = m >> 4;
        int g  = m & 7;
        int hi = (m >> 3) & 1;
        int kb = kq >> 2;
        int kk = (kq & 3) * 4;
        int q  = (kk & 7) >> 1;
        int reg = hi + 2 * (kk >> 3);
        int base = ((ma * 8 + kb) * 32) * 4;
        int l0 = ((g * 4 + q)     + kb * 4) & 31;
        int l1 = ((g * 4 + q + 1) + kb * 4) & 31;
        As[base + l0 * 4 + reg] = u0;
        As[base + l1 * 4 + reg] = u1;
    }
    __syncthreads();

    const int warp_m = warp >> 1;
    const int warp_n = warp & 1;

    float acc[2][8][4];
    #pragma unroll
    for (int i = 0; i < 2; i++)
        #pragma unroll
        for (int j = 0; j < 8; j++)
            #pragma unroll
            for (int r = 0; r < 4; r++) acc[i][j][r] = 0.0f;

    #pragma unroll
    for (int kb = 0; kb < 8; kb++) {
        int lane_s = (lane + kb * 4) & 31;
        unsigned a[2][4];
        #pragma unroll
        for (int i = 0; i < 2; i++) {
            int ma = warp_m * 2 + i;
            uint4 av = *(const uint4*)(As + ((ma * 8 + kb) * 32 + lane_s) * 4);
            a[i][0] = av.x; a[i][1] = av.y; a[i][2] = av.z; a[i][3] = av.w;
        }
        #pragma unroll
        for (int j = 0; j < 8; j++) {
            int na = warp_n * 8 + j;
            uint2 b2 = __ldg((const uint2*)(Wf + ((size_t)(na * 8 + kb) * 32 + lane) * 2));
            unsigned b[2] = {b2.x, b2.y};
            mma_f16(acc[0][j], a[0], b);
            mma_f16(acc[1][j], a[1], b);
        }
    }

    int g  = lane >> 2;
    int qc = lane & 3;
    #pragma unroll
    for (int i = 0; i < 2; i++) {
        int r0 = block_row + warp_m * 32 + i * 16 + g;
        int r1 = r0 + 8;
        float s0 = 1.0f, s1 = 1.0f;
        if (dinv) {
            if (r0 < M) s0 = __ldg(dinv + r0);
            if (r1 < M) s1 = __ldg(dinv + r1);
        }
        #pragma unroll
        for (int j = 0; j < 8; j++) {
            int col = warp_n * 64 + j * 8 + qc * 2;
            if (r0 < M) {
                unsigned u = pack_half2(acc[i][j][0] * s0, acc[i][j][1] * s0);
                *(unsigned*)(hs + (size_t)r0 * 128 + col) = u;
            }
            if (r1 < M) {
                unsigned u = pack_half2(acc[i][j][2] * s1, acc[i][j][3] * s1);
                *(unsigned*)(hs + (size_t)r1 * 128 + col) = u;
            }
        }
    }
}

// ---------------------------------------------------------------------------
// Aggregation + fused finalize: one warp per dst node.
//   scale_src=1: acc = dinv[d]*hs[d] + Sum dinv[s]*hs[s]
//   scale_src=0: acc = hs[d] + Sum hs[s]
//   h[d] = relu?(acc * dinv[d] + bias)      (fp16 out)
// ---------------------------------------------------------------------------
__global__ __launch_bounds__(256) void agg_kernel(
    const int* __restrict__ sorted_src, const int* __restrict__ row_ptr,
    const int* __restrict__ deg, const float* __restrict__ dinv,
    const float* __restrict__ bias, int relu, int scale_src,
    const __half* __restrict__ hs, __half* __restrict__ h_out, int M)
{
    int node = (blockIdx.x * 256 + threadIdx.x) >> 5;
    int lane = threadIdx.x & 31;
    if (node >= M) return;

    int beg = __ldg(row_ptr + node);
    int cnt = __ldg(deg + node);
    float dv_d = __ldg(dinv + node);

    const uint2* hsrow = (const uint2*)hs;   // 32 uint2 per row

    float4 acc;
    {
        float sw = scale_src ? dv_d : 1.0f;
        uint2 v = __ldg(hsrow + (size_t)node * 32 + lane);
        float2 a = __half22float2(*(__half2*)&v.x);
        float2 b = __half22float2(*(__half2*)&v.y);
        acc = make_float4(a.x * sw, a.y * sw, b.x * sw, b.y * sw);
    }

    int e = 0;
    while (e < cnt) {
        int batch = min(32, cnt - e);
        int s = (lane < batch) ? __ldg(sorted_src + beg + e + lane) : 0;
        float dv = scale_src ? __ldg(dinv + s) : 1.0f;
        int j = 0;
        for (; j + 4 <= batch; j += 4) {
            int s0 = __shfl_sync(0xffffffffu, s, j + 0);
            int s1 = __shfl_sync(0xffffffffu, s, j + 1);
            int s2 = __shfl_sync(0xffffffffu, s, j + 2);
            int s3 = __shfl_sync(0xffffffffu, s, j + 3);
            float w0 = __shfl_sync(0xffffffffu, dv, j + 0);
            float w1 = __shfl_sync(0xffffffffu, dv, j + 1);
            float w2 = __shfl_sync(0xffffffffu, dv, j + 2);
            float w3 = __shfl_sync(0xffffffffu, dv, j + 3);
            uint2 v0 = __ldg(hsrow + (size_t)s0 * 32 + lane);
            uint2 v1 = __ldg(hsrow + (size_t)s1 * 32 + lane);
            uint2 v2 = __ldg(hsrow + (size_t)s2 * 32 + lane);
            uint2 v3 = __ldg(hsrow + (size_t)s3 * 32 + lane);
            float2 a0 = __half22float2(*(__half2*)&v0.x), b0 = __half22float2(*(__half2*)&v0.y);
            float2 a1 = __half22float2(*(__half2*)&v1.x), b1 = __half22float2(*(__half2*)&v1.y);
            float2 a2 = __half22float2(*(__half2*)&v2.x), b2 = __half22float2(*(__half2*)&v2.y);
            float2 a3 = __half22float2(*(__half2*)&v3.x), b3 = __half22float2(*(__half2*)&v3.y);
            acc.x = fmaf(w0, a0.x, fmaf(w1, a1.x, fmaf(w2, a2.x, fmaf(w3, a3.x, acc.x))));
            acc.y = fmaf(w0, a0.y, fmaf(w1, a1.y, fmaf(w2, a2.y, fmaf(w3, a3.y, acc.y))));
            acc.z = fmaf(w0, b0.x, fmaf(w1, b1.x, fmaf(w2, b2.x, fmaf(w3, b3.x, acc.z))));
            acc.w = fmaf(w0, b0.y, fmaf(w1, b1.y, fmaf(w2, b2.y, fmaf(w3, b3.y, acc.w))));
        }
        for (; j < batch; j++) {
            int sj = __shfl_sync(0xffffffffu, s, j);
            float wj = __shfl_sync(0xffffffffu, dv, j);
            uint2 v = __ldg(hsrow + (size_t)sj * 32 + lane);
            float2 a = __half22float2(*(__half2*)&v.x);
            float2 b = __half22float2(*(__half2*)&v.y);
            acc.x = fmaf(wj, a.x, acc.x); acc.y = fmaf(wj, a.y, acc.y);
            acc.z = fmaf(wj, b.x, acc.z); acc.w = fmaf(wj, b.y, acc.w);
        }
        e += batch;
    }

    // fused finalize
    float4 bb = *((const float4*)bias + lane);
    float h0 = acc.x * dv_d + bb.x;
    float h1 = acc.y * dv_d + bb.y;
    float h2 = acc.z * dv_d + bb.z;
    float h3 = acc.w * dv_d + bb.w;
    if (relu) {
        h0 = fmaxf(h0, 0.f); h1 = fmaxf(h1, 0.f);
        h2 = fmaxf(h2, 0.f); h3 = fmaxf(h3, 0.f);
    }
    uint2 o;
    o.x = pack_half2(h0, h1);
    o.y = pack_half2(h2, h3);
    *((uint2*)h_out + (size_t)node * 32 + lane) = o;
}

// ---------------------------------------------------------------------------
// Output GEMM (tensor core): out[M,40] = A(half)[M,128] @ Wout + bout
// Block 128 rows, 8 warps, each warp 16 rows x 40 cols (5 na blocks).
// ---------------------------------------------------------------------------
__global__ __launch_bounds__(256, 2) void gemm_out_tc_kernel(
    const __half* __restrict__ A, const unsigned* __restrict__ Wf,
    const float* __restrict__ bout, float* __restrict__ out, int M)
{
    extern __shared__ unsigned As[];   // 32KB, same frag layout

    const int tid  = threadIdx.x;
    const int lane = tid & 31;
    const int warp = tid >> 5;
    const int block_row = blockIdx.x * 128;

    #pragma unroll
    for (int it = 0; it < 16; it++) {
        int idx = it * 256 + tid;
        int m  = idx >> 5;
        int kq = idx & 31;
        int grow = block_row + m;
        unsigned u0 = 0, u1 = 0;
        if (grow < M) {
            uint2 v = *(const uint2*)(A + (size_t)grow * 128 + kq * 4);
            u0 = v.x; u1 = v.y;
        }
        int ma = m >> 4;
        int g  = m & 7;
        int hi = (m >> 3) & 1;
        int kb = kq >> 2;
        int kk = (kq & 3) * 4;
        int q  = (kk & 7) >> 1;
        int reg = hi + 2 * (kk >> 3);
        int base = ((ma * 8 + kb) * 32) * 4;
        int l0 = ((g * 4 + q)     + kb * 4) & 31;
        int l1 = ((g * 4 + q + 1) + kb * 4) & 31;
        As[base + l0 * 4 + reg] = u0;
        As[base + l1 * 4 + reg] = u1;
    }
    __syncthreads();

    const int ma = warp;   // each warp: 16 rows

    float acc[5][4];
    #pragma unroll
    for (int j = 0; j < 5; j++)
        #pragma unroll
        for (int r = 0; r < 4; r++) acc[j][r] = 0.0f;

    #pragma unroll
    for (int kb = 0; kb < 8; kb++) {
        int lane_s = (lane + kb * 4) & 31;
        uint4 av = *(const uint4*)(As + ((ma * 8 + kb) * 32 + lane_s) * 4);
        unsigned a[4] = {av.x, av.y, av.z, av.w};
        #pragma unroll
        for (int j = 0; j < 5; j++) {
            uint2 b2 = __ldg((const uint2*)(Wf + ((size_t)(j * 8 + kb) * 32 + lane) * 2));
            unsigned b[2] = {b2.x, b2.y};
            mma_f16(acc[j], a, b);
        }
    }

    int g  = lane >> 2;
    int qc = lane & 3;
    int r0 = block_row + ma * 16 + g;
    int r1 = r0 + 8;
    #pragma unroll
    for (int j = 0; j < 5; j++) {
        int c0 = j * 8 + qc * 2;
        float b0 = __ldg(bout + c0);
        float b1 = __ldg(bout + c0 + 1);
        if (r0 < M) {
            float2 o = make_float2(acc[j][0] + b0, acc[j][1] + b1);
            *(float2*)(out + (size_t)r0 * 40 + c0) = o;
        }
        if (r1 < M) {
            float2 o = make_float2(acc[j][2] + b0, acc[j][3] + b1);
            *(float2*)(out + (size_t)r1 * 40 + c0) = o;
        }
    }
}

// ---------------------------------------------------------------------------

extern "C" void kernel_launch(void* const* d_in, const int* in_sizes, int n_in,
                              void* d_out, int out_size)
{
    const float* x    = (const float*)d_in[0];
    const int*   ei   = (const int*)d_in[1];
    const float* W1   = (const float*)d_in[2];
    const float* b1   = (const float*)d_in[3];
    const float* W2   = (const float*)d_in[4];
    const float* b2   = (const float*)d_in[5];
    const float* Wout = (const float*)d_in[6];
    const float* bout = (const float*)d_in[7];
    float* out = (float*)d_out;

    const int M = in_sizes[0] / FDIM;
    const int E = in_sizes[1] / 2;
    const int* src = ei;
    const int* dst = ei + E;

    __half *bufH, *bufH2;
    float *dinv;
    unsigned *w1f, *w2f, *wof;
    int *deg, *cursor, *rowptr, *bsum, *srcsorted;
    cudaGetSymbolAddress((void**)&bufH, g_bufH);
    cudaGetSymbolAddress((void**)&bufH2, g_bufH2);
    cudaGetSymbolAddress((void**)&dinv, g_dinv);
    cudaGetSymbolAddress((void**)&deg, g_deg);
    cudaGetSymbolAddress((void**)&cursor, g_cursor);
    cudaGetSymbolAddress((void**)&rowptr, g_rowptr);
    cudaGetSymbolAddress((void**)&bsum, g_bsum);
    cudaGetSymbolAddress((void**)&srcsorted, g_srcsorted);
    cudaGetSymbolAddress((void**)&w1f, g_W1f);
    cudaGetSymbolAddress((void**)&w2f, g_W2f);
    cudaGetSymbolAddress((void**)&wof, g_Wof);

    static int inited = 0;
    static cudaStream_t s2;
    static cudaEvent_t evFork, evJoin;
    if (!inited) {
        cudaFuncSetAttribute(gemm_f16_kernel,
                             cudaFuncAttributeMaxDynamicSharedMemorySize, 32768);
        cudaFuncSetAttribute(gemm_out_tc_kernel,
                             cudaFuncAttributeMaxDynamicSharedMemorySize, 32768);
        cudaStreamCreateWithFlags(&s2, cudaStreamNonBlocking);
        cudaEventCreateWithFlags(&evFork, cudaEventDisableTiming);
        cudaEventCreateWithFlags(&evJoin, cudaEventDisableTiming);
        inited = 1;
    }

    const int nb_nodes = (M + 255) / 256;
    const int nb_edges = (E + 255) / 256;
    const int nb_edge4 = (E + 1023) / 1024;
    const int nb_scan  = (M + 1023) / 1024;
    const int nb_gemm  = (M + 127) / 128;
    const int nb_agg   = (M + 7) / 8;

    // --- fork: ENTIRE CSR chain + dinv on s2, overlapped with wprep + gemm1 ---
    cudaEventRecord(evFork, 0);
    cudaStreamWaitEvent(s2, evFork, 0);
    zero_kernel<<<nb_nodes, 256, 0, s2>>>(deg, M);
    deg_count_kernel<<<nb_edge4, 256, 0, s2>>>(dst, deg, E);
    dinv_kernel<<<nb_nodes, 256, 0, s2>>>(deg, dinv, M);
    scan_block_kernel<<<nb_scan, 1024, 0, s2>>>(deg, rowptr, bsum, M);
    scan_sums_kernel<<<1, 32, 0, s2>>>(bsum, nb_scan);
    add_offsets_kernel<<<nb_nodes, 256, 0, s2>>>(rowptr, cursor, bsum, M);
    bin_edges_kernel<<<nb_edges, 256, 0, s2>>>(src, dst, cursor, srcsorted, E);
    cudaEventRecord(evJoin, s2);

    // --- main: W prep + layer-1 GEMM (unscaled hs1; NO dinv dependency) ---
    wprep_kernel<<<64, 256>>>(W1, w1f, 128);
    wprep_kernel<<<64, 256>>>(W2, w2f, 128);
    wprep_kernel<<<20, 256>>>(Wout, wof, 40);
    gemm_f16_kernel<<<nb_gemm, 256, 32768>>>(x, 0, w1f, nullptr, bufH, M);

    // --- join; layer-1 aggregation (src-scaled) + finalize -> h1 (fp16) ---
    cudaStreamWaitEvent(0, evJoin, 0);
    agg_kernel<<<nb_agg, 256>>>(srcsorted, rowptr, deg, dinv, b1, 1, 1, bufH, bufH2, M);

    // --- Layer 2: hs2 pre-scaled; agg2 pure sum -> h2 (fp16) ---
    gemm_f16_kernel<<<nb_gemm, 256, 32768>>>(bufH2, 1, w2f, dinv, bufH, M);
    agg_kernel<<<nb_agg, 256>>>(srcsorted, rowptr, deg, dinv, b2, 0, 0, bufH, bufH2, M);

    // --- Output projection (tensor core): out = h2 @ Wout + bout ---
    gemm_out_tc_kernel<<<nb_gemm, 256, 32768>>>(bufH2, wof, bout, out, M);
}

// round 12
// speedup vs baseline: 1.5125x; 1.0441x over previous
#include <cuda_runtime.h>
#include <cuda_bf16.h>
#include <cuda_fp16.h>
#include <cstdint>

// ---------------------------------------------------------------------------
// GCN: 3 layers, N=100000, E=1.6M, self-loops, sym-norm.
//   Layer 1: hs1 = x @ W1 (UNscaled fp16) ; h1 = relu(dinv_d*(Sum dinv_s*hs1_s) + b1)
//   Layer 2: hs2 = (h1 @ W2)*dinv_row     ; h2 = dinv_d*(Sum hs2_s) + b2
//   Out:     out = h2 @ Wout + bout        (fp16 mma, N=40)
// CSR build fully overlapped with layer-1 GEMM on a forked stream.
// GEMMs: ldmatrix-staged A (swizzled row-major smem), W b-frags from gmem.
// ---------------------------------------------------------------------------

#define MAXN 100352
#define MAXE 1700000
#define FDIM 128

__device__ __half g_bufH[MAXN * FDIM];    // hs (fp16)
__device__ __half g_bufH2[MAXN * FDIM];   // h (fp16, finished layer output)
__device__ float  g_dinv[MAXN];
__device__ int    g_deg[MAXN];
__device__ int    g_cursor[MAXN];
__device__ int    g_rowptr[MAXN];
__device__ int    g_bsum[256];
__device__ int    g_srcsorted[MAXE];
// fp16 b-fragments: [na][kb(8)][lane(32)][reg(2)] of uint(=half2)
__device__ unsigned g_W1f[8192];
__device__ unsigned g_W2f[8192];
__device__ unsigned g_Wof[2560];          // Wout: na(5) blocks

// ---------------------------------------------------------------------------
__device__ __forceinline__ unsigned pack_half2(float x, float y) {
    __half2 h = __floats2half2_rn(x, y);
    unsigned u;
    asm("mov.b32 %0, %1;" : "=r"(u) : "r"(*(unsigned*)&h));
    return u;
}

__device__ __forceinline__ void mma_f16(float* d, const unsigned* a, const unsigned* b) {
    asm volatile(
        "mma.sync.aligned.m16n8k16.row.col.f32.f16.f16.f32 "
        "{%0,%1,%2,%3}, {%4,%5,%6,%7}, {%8,%9}, {%0,%1,%2,%3};\n"
        : "+f"(d[0]), "+f"(d[1]), "+f"(d[2]), "+f"(d[3])
        : "r"(a[0]), "r"(a[1]), "r"(a[2]), "r"(a[3]), "r"(b[0]), "r"(b[1]));
}

__device__ __forceinline__ void ldsm_x4(unsigned* r, uint32_t addr) {
    asm volatile(
        "ldmatrix.sync.aligned.m8n8.x4.shared.b16 {%0,%1,%2,%3}, [%4];"
        : "=r"(r[0]), "=r"(r[1]), "=r"(r[2]), "=r"(r[3]) : "r"(addr));
}

// ---------------------------------------------------------------------------
// CSR construction
// ---------------------------------------------------------------------------
__global__ void zero_kernel(int* deg, int M) {
    int i = blockIdx.x * blockDim.x + threadIdx.x;
    if (i < M) deg[i] = 0;
}

__global__ void deg_count_kernel(const int* __restrict__ dst, int* deg, int E) {
    int i = (blockIdx.x * blockDim.x + threadIdx.x) * 4;
    if (i + 3 < E) {
        int4 d = *(const int4*)(dst + i);
        atomicAdd(&deg[d.x], 1);
        atomicAdd(&deg[d.y], 1);
        atomicAdd(&deg[d.z], 1);
        atomicAdd(&deg[d.w], 1);
    } else {
        for (int j = i; j < E; j++) atomicAdd(&deg[dst[j]], 1);
    }
}

__global__ void dinv_kernel(const int* __restrict__ deg, float* dinv, int M) {
    int i = blockIdx.x * blockDim.x + threadIdx.x;
    if (i < M) dinv[i] = rsqrtf((float)deg[i] + 1.0f);
}

__global__ __launch_bounds__(1024) void scan_block_kernel(
    const int* __restrict__ deg, int* row_ptr, int* bsum, int M)
{
    int gid  = blockIdx.x * 1024 + threadIdx.x;
    int lane = threadIdx.x & 31;
    int wid  = threadIdx.x >> 5;
    int v = (gid < M) ? deg[gid] : 0;
    int x = v;
    #pragma unroll
    for (int o = 1; o < 32; o <<= 1) {
        int t = __shfl_up_sync(0xffffffffu, x, o);
        if (lane >= o) x += t;
    }
    __shared__ int ws[32];
    if (lane == 31) ws[wid] = x;
    __syncthreads();
    if (wid == 0) {
        int y = ws[lane];
        #pragma unroll
        for (int o = 1; o < 32; o <<= 1) {
            int t = __shfl_up_sync(0xffffffffu, y, o);
            if (lane >= o) y += t;
        }
        ws[lane] = y;
    }
    __syncthreads();
    int base = (wid > 0) ? ws[wid - 1] : 0;
    int incl = base + x;
    if (gid < M) row_ptr[gid] = incl - v;
    if (threadIdx.x == 1023) bsum[blockIdx.x] = incl;
}

__global__ void scan_sums_kernel(int* bsum, int nb) {
    int lane = threadIdx.x;
    int v[4];
    int base_i = lane * 4;
    #pragma unroll
    for (int j = 0; j < 4; j++)
        v[j] = (base_i + j < nb) ? bsum[base_i + j] : 0;
    int s = v[0] + v[1] + v[2] + v[3];
    int x = s;
    #pragma unroll
    for (int o = 1; o < 32; o <<= 1) {
        int t = __shfl_up_sync(0xffffffffu, x, o);
        if (lane >= o) x += t;
    }
    int excl = x - s;
    int run = excl;
    #pragma unroll
    for (int j = 0; j < 4; j++) {
        if (base_i + j < nb) bsum[base_i + j] = run;
        run += v[j];
    }
}

__global__ void add_offsets_kernel(int* row_ptr, int* cursor,
                                   const int* __restrict__ bsum, int M) {
    int gid = blockIdx.x * blockDim.x + threadIdx.x;
    if (gid < M) {
        int v = row_ptr[gid] + bsum[gid >> 10];
        row_ptr[gid] = v;
        cursor[gid]  = v;
    }
}

__global__ void bin_edges_kernel(const int* __restrict__ src, const int* __restrict__ dst,
                                 int* cursor, int* sorted_src, int E)
{
    int i = blockIdx.x * blockDim.x + threadIdx.x;
    if (i >= E) return;
    int pos = atomicAdd(&cursor[dst[i]], 1);
    sorted_src[pos] = src[i];
}

// ---------------------------------------------------------------------------
// W fragment prep (fp32 [K][N] -> fp16 b-frags), N = 128 or 40.
// ---------------------------------------------------------------------------
__global__ void wprep_kernel(const float* __restrict__ W, unsigned* Wf, int N) {
    int idx = blockIdx.x * blockDim.x + threadIdx.x;
    if (idx >= 128 * N) return;
    int k = idx / N;
    int n = idx % N;
    __half w = __float2half_rn(W[idx]);
    int na = n >> 3, g = n & 7;
    int kb = k >> 4, kk = k & 15;
    int q = (kk & 7) >> 1, reg = kk >> 3, h = kk & 1;
    int lane = g * 4 + q;
    __half* out = (__half*)Wf;
    out[(((na * 8 + kb) * 32 + lane) * 2 + reg) * 2 + h] = w;
}

// ---------------------------------------------------------------------------
// fp16 tensor-core GEMM: hs(half) = A[M,128] @ W[128,128] (* dinv[row] if dinv).
// A staged row-major in smem (16B-chunk XOR swizzle), a-frags via ldmatrix.x4.
// Block 128 rows, 8 warps, warp grid 4(M)x2(N), warp tile 32x64.
// ---------------------------------------------------------------------------
__global__ __launch_bounds__(256, 2) void gemm_f16_kernel(
    const void* __restrict__ Ap, int a_is_half, const unsigned* __restrict__ Wf,
    const float* __restrict__ dinv, __half* __restrict__ hs, int M)
{
    extern __shared__ unsigned char smem_raw[];   // 32KB: 128 rows x 256B
    const int tid  = threadIdx.x;
    const int lane = tid & 31;
    const int warp = tid >> 5;
    const int block_row = blockIdx.x * 128;
    uint32_t smem_u32 = (uint32_t)__cvta_generic_to_shared(smem_raw);

    // ---- stage A tile: row-major half, chunk swizzle c^(m&7); 8 STS.128/thread ----
    #pragma unroll
    for (int it = 0; it < 8; it++) {
        int idx = it * 256 + tid;
        int m = idx >> 4;        // row 0..127
        int c = idx & 15;        // 16B chunk 0..15
        int grow = block_row + m;
        uint4 u = make_uint4(0, 0, 0, 0);
        if (grow < M) {
            if (a_is_half) {
                u = *(const uint4*)((const __half*)Ap + (size_t)grow * 128 + c * 8);
            } else {
                const float* ap = (const float*)Ap + (size_t)grow * 128 + c * 8;
                float4 v0 = *(const float4*)ap;
                float4 v1 = *(const float4*)(ap + 4);
                u.x = pack_half2(v0.x, v0.y);
                u.y = pack_half2(v0.z, v0.w);
                u.z = pack_half2(v1.x, v1.y);
                u.w = pack_half2(v1.z, v1.w);
            }
        }
        int cs = c ^ (m & 7);
        *(uint4*)(smem_raw + m * 256 + cs * 16) = u;
    }
    __syncthreads();

    // ---- mainloop ----
    const int warp_m = warp >> 1;
    const int warp_n = warp & 1;

    float acc[2][8][4];
    #pragma unroll
    for (int i = 0; i < 2; i++)
        #pragma unroll
        for (int j = 0; j < 8; j++)
            #pragma unroll
            for (int r = 0; r < 4; r++) acc[i][j][r] = 0.0f;

    // ldmatrix lane->address precompute parts
    const int lrow = (lane & 7) + ((lane >> 3) & 1) * 8;   // row within 16-row tile
    const int lcol = lane >> 4;                            // 0/1: k-halves

    #pragma unroll
    for (int kb = 0; kb < 8; kb++) {
        unsigned a[2][4];
        #pragma unroll
        for (int i = 0; i < 2; i++) {
            int mrow = (warp_m * 2 + i) * 16 + lrow;
            int c = kb * 2 + lcol;
            int cs = c ^ (mrow & 7);
            ldsm_x4(a[i], smem_u32 + mrow * 256 + cs * 16);
        }
        #pragma unroll
        for (int j = 0; j < 8; j++) {
            int na = warp_n * 8 + j;
            uint2 b2 = __ldg((const uint2*)(Wf + ((size_t)(na * 8 + kb) * 32 + lane) * 2));
            unsigned b[2] = {b2.x, b2.y};
            mma_f16(acc[0][j], a[0], b);
            mma_f16(acc[1][j], a[1], b);
        }
    }

    // ---- epilogue: optional dinv row scale, store fp16 ----
    int g  = lane >> 2;
    int qc = lane & 3;
    #pragma unroll
    for (int i = 0; i < 2; i++) {
        int r0 = block_row + warp_m * 32 + i * 16 + g;
        int r1 = r0 + 8;
        float s0 = 1.0f, s1 = 1.0f;
        if (dinv) {
            if (r0 < M) s0 = __ldg(dinv + r0);
            if (r1 < M) s1 = __ldg(dinv + r1);
        }
        #pragma unroll
        for (int j = 0; j < 8; j++) {
            int col = warp_n * 64 + j * 8 + qc * 2;
            if (r0 < M) {
                unsigned u = pack_half2(acc[i][j][0] * s0, acc[i][j][1] * s0);
                *(unsigned*)(hs + (size_t)r0 * 128 + col) = u;
            }
            if (r1 < M) {
                unsigned u = pack_half2(acc[i][j][2] * s1, acc[i][j][3] * s1);
                *(unsigned*)(hs + (size_t)r1 * 128 + col) = u;
            }
        }
    }
}

// ---------------------------------------------------------------------------
// Aggregation + fused finalize: one warp per dst node.
//   scale_src=1: acc = dinv[d]*hs[d] + Sum dinv[s]*hs[s]
//   scale_src=0: acc = hs[d] + Sum hs[s]
//   h[d] = relu?(acc * dinv[d] + bias)      (fp16 out)
// ---------------------------------------------------------------------------
__global__ __launch_bounds__(256) void agg_kernel(
    const int* __restrict__ sorted_src, const int* __restrict__ row_ptr,
    const int* __restrict__ deg, const float* __restrict__ dinv,
    const float* __restrict__ bias, int relu, int scale_src,
    const __half* __restrict__ hs, __half* __restrict__ h_out, int M)
{
    int node = (blockIdx.x * 256 + threadIdx.x) >> 5;
    int lane = threadIdx.x & 31;
    if (node >= M) return;

    int beg = __ldg(row_ptr + node);
    int cnt = __ldg(deg + node);
    float dv_d = __ldg(dinv + node);

    const uint2* hsrow = (const uint2*)hs;   // 32 uint2 per row

    float4 acc;
    {
        float sw = scale_src ? dv_d : 1.0f;
        uint2 v = __ldg(hsrow + (size_t)node * 32 + lane);
        float2 a = __half22float2(*(__half2*)&v.x);
        float2 b = __half22float2(*(__half2*)&v.y);
        acc = make_float4(a.x * sw, a.y * sw, b.x * sw, b.y * sw);
    }

    int e = 0;
    while (e < cnt) {
        int batch = min(32, cnt - e);
        int s = (lane < batch) ? __ldg(sorted_src + beg + e + lane) : 0;
        float dv = scale_src ? __ldg(dinv + s) : 1.0f;
        int j = 0;
        for (; j + 4 <= batch; j += 4) {
            int s0 = __shfl_sync(0xffffffffu, s, j + 0);
            int s1 = __shfl_sync(0xffffffffu, s, j + 1);
            int s2 = __shfl_sync(0xffffffffu, s, j + 2);
            int s3 = __shfl_sync(0xffffffffu, s, j + 3);
            float w0 = __shfl_sync(0xffffffffu, dv, j + 0);
            float w1 = __shfl_sync(0xffffffffu, dv, j + 1);
            float w2 = __shfl_sync(0xffffffffu, dv, j + 2);
            float w3 = __shfl_sync(0xffffffffu, dv, j + 3);
            uint2 v0 = __ldg(hsrow + (size_t)s0 * 32 + lane);
            uint2 v1 = __ldg(hsrow + (size_t)s1 * 32 + lane);
            uint2 v2 = __ldg(hsrow + (size_t)s2 * 32 + lane);
            uint2 v3 = __ldg(hsrow + (size_t)s3 * 32 + lane);
            float2 a0 = __half22float2(*(__half2*)&v0.x), b0 = __half22float2(*(__half2*)&v0.y);
            float2 a1 = __half22float2(*(__half2*)&v1.x), b1 = __half22float2(*(__half2*)&v1.y);
            float2 a2 = __half22float2(*(__half2*)&v2.x), b2 = __half22float2(*(__half2*)&v2.y);
            float2 a3 = __half22float2(*(__half2*)&v3.x), b3 = __half22float2(*(__half2*)&v3.y);
            acc.x = fmaf(w0, a0.x, fmaf(w1, a1.x, fmaf(w2, a2.x, fmaf(w3, a3.x, acc.x))));
            acc.y = fmaf(w0, a0.y, fmaf(w1, a1.y, fmaf(w2, a2.y, fmaf(w3, a3.y, acc.y))));
            acc.z = fmaf(w0, b0.x, fmaf(w1, b1.x, fmaf(w2, b2.x, fmaf(w3, b3.x, acc.z))));
            acc.w = fmaf(w0, b0.y, fmaf(w1, b1.y, fmaf(w2, b2.y, fmaf(w3, b3.y, acc.w))));
        }
        for (; j < batch; j++) {
            int sj = __shfl_sync(0xffffffffu, s, j);
            float wj = __shfl_sync(0xffffffffu, dv, j);
            uint2 v = __ldg(hsrow + (size_t)sj * 32 + lane);
            float2 a = __half22float2(*(__half2*)&v.x);
            float2 b = __half22float2(*(__half2*)&v.y);
            acc.x = fmaf(wj, a.x, acc.x); acc.y = fmaf(wj, a.y, acc.y);
            acc.z = fmaf(wj, b.x, acc.z); acc.w = fmaf(wj, b.y, acc.w);
        }
        e += batch;
    }

    // fused finalize
    float4 bb = *((const float4*)bias + lane);
    float h0 = acc.x * dv_d + bb.x;
    float h1 = acc.y * dv_d + bb.y;
    float h2 = acc.z * dv_d + bb.z;
    float h3 = acc.w * dv_d + bb.w;
    if (relu) {
        h0 = fmaxf(h0, 0.f); h1 = fmaxf(h1, 0.f);
        h2 = fmaxf(h2, 0.f); h3 = fmaxf(h3, 0.f);
    }
    uint2 o;
    o.x = pack_half2(h0, h1);
    o.y = pack_half2(h2, h3);
    *((uint2*)h_out + (size_t)node * 32 + lane) = o;
}

// ---------------------------------------------------------------------------
// Output GEMM (tensor core): out[M,40] = A(half)[M,128] @ Wout + bout
// ldmatrix-staged A; block 128 rows, 8 warps, warp: 16 rows x 40 cols.
// ---------------------------------------------------------------------------
__global__ __launch_bounds__(256, 2) void gemm_out_tc_kernel(
    const __half* __restrict__ A, const unsigned* __restrict__ Wf,
    const float* __restrict__ bout, float* __restrict__ out, int M)
{
    extern __shared__ unsigned char smem_raw[];   // 32KB
    const int tid  = threadIdx.x;
    const int lane = tid & 31;
    const int warp = tid >> 5;
    const int block_row = blockIdx.x * 128;
    uint32_t smem_u32 = (uint32_t)__cvta_generic_to_shared(smem_raw);

    #pragma unroll
    for (int it = 0; it < 8; it++) {
        int idx = it * 256 + tid;
        int m = idx >> 4;
        int c = idx & 15;
        int grow = block_row + m;
        uint4 u = make_uint4(0, 0, 0, 0);
        if (grow < M)
            u = *(const uint4*)(A + (size_t)grow * 128 + c * 8);
        int cs = c ^ (m & 7);
        *(uint4*)(smem_raw + m * 256 + cs * 16) = u;
    }
    __syncthreads();

    const int ma = warp;   // each warp: 16 rows
    const int lrow = (lane & 7) + ((lane >> 3) & 1) * 8;
    const int lcol = lane >> 4;

    float acc[5][4];
    #pragma unroll
    for (int j = 0; j < 5; j++)
        #pragma unroll
        for (int r = 0; r < 4; r++) acc[j][r] = 0.0f;

    #pragma unroll
    for (int kb = 0; kb < 8; kb++) {
        unsigned a[4];
        {
            int mrow = ma * 16 + lrow;
            int c = kb * 2 + lcol;
            int cs = c ^ (mrow & 7);
            ldsm_x4(a, smem_u32 + mrow * 256 + cs * 16);
        }
        #pragma unroll
        for (int j = 0; j < 5; j++) {
            uint2 b2 = __ldg((const uint2*)(Wf + ((size_t)(j * 8 + kb) * 32 + lane) * 2));
            unsigned b[2] = {b2.x, b2.y};
            mma_f16(acc[j], a, b);
        }
    }

    int g  = lane >> 2;
    int qc = lane & 3;
    int r0 = block_row + ma * 16 + g;
    int r1 = r0 + 8;
    #pragma unroll
    for (int j = 0; j < 5; j++) {
        int c0 = j * 8 + qc * 2;
        float b0 = __ldg(bout + c0);
        float b1 = __ldg(bout + c0 + 1);
        if (r0 < M) {
            float2 o = make_float2(acc[j][0] + b0, acc[j][1] + b1);
            *(float2*)(out + (size_t)r0 * 40 + c0) = o;
        }
        if (r1 < M) {
            float2 o = make_float2(acc[j][2] + b0, acc[j][3] + b1);
            *(float2*)(out + (size_t)r1 * 40 + c0) = o;
        }
    }
}

// ---------------------------------------------------------------------------

extern "C" void kernel_launch(void* const* d_in, const int* in_sizes, int n_in,
                              void* d_out, int out_size)
{
    const float* x    = (const float*)d_in[0];
    const int*   ei   = (const int*)d_in[1];
    const float* W1   = (const float*)d_in[2];
    const float* b1   = (const float*)d_in[3];
    const float* W2   = (const float*)d_in[4];
    const float* b2   = (const float*)d_in[5];
    const float* Wout = (const float*)d_in[6];
    const float* bout = (const float*)d_in[7];
    float* out = (float*)d_out;

    const int M = in_sizes[0] / FDIM;
    const int E = in_sizes[1] / 2;
    const int* src = ei;
    const int* dst = ei + E;

    __half *bufH, *bufH2;
    float *dinv;
    unsigned *w1f, *w2f, *wof;
    int *deg, *cursor, *rowptr, *bsum, *srcsorted;
    cudaGetSymbolAddress((void**)&bufH, g_bufH);
    cudaGetSymbolAddress((void**)&bufH2, g_bufH2);
    cudaGetSymbolAddress((void**)&dinv, g_dinv);
    cudaGetSymbolAddress((void**)&deg, g_deg);
    cudaGetSymbolAddress((void**)&cursor, g_cursor);
    cudaGetSymbolAddress((void**)&rowptr, g_rowptr);
    cudaGetSymbolAddress((void**)&bsum, g_bsum);
    cudaGetSymbolAddress((void**)&srcsorted, g_srcsorted);
    cudaGetSymbolAddress((void**)&w1f, g_W1f);
    cudaGetSymbolAddress((void**)&w2f, g_W2f);
    cudaGetSymbolAddress((void**)&wof, g_Wof);

    static int inited = 0;
    static cudaStream_t s2;
    static cudaEvent_t evFork, evJoin;
    if (!inited) {
        cudaFuncSetAttribute(gemm_f16_kernel,
                             cudaFuncAttributeMaxDynamicSharedMemorySize, 32768);
        cudaFuncSetAttribute(gemm_out_tc_kernel,
                             cudaFuncAttributeMaxDynamicSharedMemorySize, 32768);
        cudaStreamCreateWithFlags(&s2, cudaStreamNonBlocking);
        cudaEventCreateWithFlags(&evFork, cudaEventDisableTiming);
        cudaEventCreateWithFlags(&evJoin, cudaEventDisableTiming);
        inited = 1;
    }

    const int nb_nodes = (M + 255) / 256;
    const int nb_edges = (E + 255) / 256;
    const int nb_edge4 = (E + 1023) / 1024;
    const int nb_scan  = (M + 1023) / 1024;
    const int nb_gemm  = (M + 127) / 128;
    const int nb_agg   = (M + 7) / 8;

    // --- fork: ENTIRE CSR chain + dinv on s2, overlapped with wprep + gemm1 ---
    cudaEventRecord(evFork, 0);
    cudaStreamWaitEvent(s2, evFork, 0);
    zero_kernel<<<nb_nodes, 256, 0, s2>>>(deg, M);
    deg_count_kernel<<<nb_edge4, 256, 0, s2>>>(dst, deg, E);
    dinv_kernel<<<nb_nodes, 256, 0, s2>>>(deg, dinv, M);
    scan_block_kernel<<<nb_scan, 1024, 0, s2>>>(deg, rowptr, bsum, M);
    scan_sums_kernel<<<1, 32, 0, s2>>>(bsum, nb_scan);
    add_offsets_kernel<<<nb_nodes, 256, 0, s2>>>(rowptr, cursor, bsum, M);
    bin_edges_kernel<<<nb_edges, 256, 0, s2>>>(src, dst, cursor, srcsorted, E);
    cudaEventRecord(evJoin, s2);

    // --- main: W prep + layer-1 GEMM (unscaled hs1; NO dinv dependency) ---
    wprep_kernel<<<64, 256>>>(W1, w1f, 128);
    wprep_kernel<<<64, 256>>>(W2, w2f, 128);
    wprep_kernel<<<20, 256>>>(Wout, wof, 40);
    gemm_f16_kernel<<<nb_gemm, 256, 32768>>>(x, 0, w1f, nullptr, bufH, M);

    // --- join; layer-1 aggregation (src-scaled) + finalize -> h1 (fp16) ---
    cudaStreamWaitEvent(0, evJoin, 0);
    agg_kernel<<<nb_agg, 256>>>(srcsorted, rowptr, deg, dinv, b1, 1, 1, bufH, bufH2, M);

    // --- Layer 2: hs2 pre-scaled; agg2 pure sum -> h2 (fp16) ---
    gemm_f16_kernel<<<nb_gemm, 256, 32768>>>(bufH2, 1, w2f, dinv, bufH, M);
    agg_kernel<<<nb_agg, 256>>>(srcsorted, rowptr, deg, dinv, b2, 0, 0, bufH, bufH2, M);

    // --- Output projection (tensor core): out = h2 @ Wout + bout ---
    gemm_out_tc_kernel<<<nb_gemm, 256, 32768>>>(bufH2, wof, bout, out, M);
}